// round 6
// baseline (speedup 1.0000x reference)
#include <cuda_runtime.h>
#include <cstdint>

#define NN 100000

// ---------------- scratch: static __device__ globals ----------------
__device__ float g_dinv[NN];           // deg -> dinv
__device__ float g_hs1 [NN * 64];      // (x@W1)*dinv
__device__ float g_acc1[NN * 64];      // scatter target (init = hs1: self-loop)
__device__ float g_h1d [NN * 64];      // relu+dropout output
__device__ float g_hs2 [NN * 32];
__device__ float g_acc2[NN * 32];
__device__ unsigned g_oddor;           // ==0 -> edge_index int64, !=0 -> int32

// ---------------- edge index accessor (dtype decided at runtime) ----------------
__device__ __forceinline__ int edge_at(const void* ei, int is64, long long idx) {
    if (is64) return (int)((const long long*)ei)[idx];
    return ((const int*)ei)[idx];
}

// ---------------- dtype detection ----------------
__global__ void reset_flag_kernel() { g_oddor = 0u; }

__global__ void detect_kernel(const unsigned* w, long long nwords) {
    long long stride = (long long)gridDim.x * blockDim.x;
    unsigned acc = 0;
    for (long long i = (long long)blockIdx.x * blockDim.x + threadIdx.x;
         2 * i + 1 < nwords; i += stride)
        acc |= w[2 * i + 1];
    for (int o = 16; o > 0; o >>= 1) acc |= __shfl_down_sync(0xffffffffu, acc, o);
    if ((threadIdx.x & 31) == 0 && acc) atomicOr(&g_oddor, acc);
}

// ---------------- JAX Threefry-2x32, key = (0, 42) ----------------
__device__ __forceinline__ void threefry_0_42(uint32_t c0, uint32_t c1,
                                              uint32_t& o0, uint32_t& o1) {
    const uint32_t ks0 = 0u;
    const uint32_t ks1 = 42u;
    const uint32_t ks2 = 0x1BD11BDAu ^ 0u ^ 42u;
    uint32_t x0 = c0 + ks0;
    uint32_t x1 = c1 + ks1;
#define TF_RND(r) { x0 += x1; x1 = (x1 << (r)) | (x1 >> (32 - (r))); x1 ^= x0; }
    TF_RND(13) TF_RND(15) TF_RND(26) TF_RND(6)
    x0 += ks1; x1 += ks2 + 1u;
    TF_RND(17) TF_RND(29) TF_RND(16) TF_RND(24)
    x0 += ks2; x1 += ks0 + 2u;
    TF_RND(13) TF_RND(15) TF_RND(26) TF_RND(6)
    x0 += ks0; x1 += ks1 + 3u;
    TF_RND(17) TF_RND(29) TF_RND(16) TF_RND(24)
    x0 += ks1; x1 += ks2 + 4u;
    TF_RND(13) TF_RND(15) TF_RND(26) TF_RND(6)
    x0 += ks2; x1 += ks0 + 5u;
#undef TF_RND
    o0 = x0; o1 = x1;
}

// keep = uniform_from_bits(bits) < 0.8  (exactly JAX's float path)
__device__ __forceinline__ bool jax_keep(uint32_t bits) {
    float f = __uint_as_float((bits >> 9) | 0x3f800000u) - 1.0f;
    return f < 0.8f;
}

// ---------------- degree / dinv ----------------
__global__ void fill_one_kernel(int n) {
    int i = blockIdx.x * blockDim.x + threadIdx.x;
    if (i < n) g_dinv[i] = 1.0f;      // self-loop folded in
}

__global__ void deg_kernel(const void* ei, int E) {
    int is64 = (g_oddor == 0u);
    int e = blockIdx.x * blockDim.x + threadIdx.x;
    if (e < E) {
        int d = edge_at(ei, is64, (long long)E + e);
        if (d >= 0 && d < NN) atomicAdd(&g_dinv[d], 1.0f);
    }
}

__global__ void rsqrt_kernel(int n) {
    int i = blockIdx.x * blockDim.x + threadIdx.x;
    if (i < n) g_dinv[i] = rsqrtf(g_dinv[i]);
}

// ---------------- GEMM layer 1: hs1 = acc1 = (X @ W1) * dinv  (K=128, C=64) ----------------
__global__ void gemm1_kernel(const float* X, const float* W) {
    __shared__ float Ws[128 * 64];          // 32 KB
    __shared__ float Xs[128 * 17];          // transposed X tile
    const int tid = threadIdx.x;
    const int n0  = blockIdx.x * 16;

    for (int i = tid; i < 128 * 64; i += 256) Ws[i] = W[i];
    for (int i = tid; i < 16 * 128; i += 256) {
        int r = i >> 7, k = i & 127;
        Xs[k * 17 + r] = X[(size_t)(n0 + r) * 128 + k];
    }
    __syncthreads();

    const int tc = tid & 15;
    const int tr = tid >> 4;
    float a0 = 0.f, a1 = 0.f, a2 = 0.f, a3 = 0.f;
#pragma unroll 4
    for (int k = 0; k < 128; ++k) {
        float xv = Xs[k * 17 + tr];
        int wb = k * 64 + tc * 4;
        a0 = fmaf(xv, Ws[wb + 0], a0);
        a1 = fmaf(xv, Ws[wb + 1], a1);
        a2 = fmaf(xv, Ws[wb + 2], a2);
        a3 = fmaf(xv, Ws[wb + 3], a3);
    }
    int n = n0 + tr;
    if (n < NN) {
        float s = g_dinv[n];
        size_t o = (size_t)n * 64 + tc * 4;
        g_hs1[o + 0] = a0 * s;  g_acc1[o + 0] = a0 * s;
        g_hs1[o + 1] = a1 * s;  g_acc1[o + 1] = a1 * s;
        g_hs1[o + 2] = a2 * s;  g_acc1[o + 2] = a2 * s;
        g_hs1[o + 3] = a3 * s;  g_acc1[o + 3] = a3 * s;
    }
}

// ---------------- GEMM layer 2: hs2 = acc2 = (h1d @ W2) * dinv  (K=64, C=32) ----------------
__global__ void gemm2_kernel(const float* W) {
    __shared__ float Ws[64 * 32];
    __shared__ float Xs[64 * 33];
    const int tid = threadIdx.x;
    const int n0  = blockIdx.x * 32;

    for (int i = tid; i < 64 * 32; i += 256) Ws[i] = W[i];
    for (int i = tid; i < 32 * 64; i += 256) {
        int r = i >> 6, k = i & 63;
        Xs[k * 33 + r] = g_h1d[(size_t)(n0 + r) * 64 + k];
    }
    __syncthreads();

    const int tc = tid & 7;
    const int tr = tid >> 3;
    float a0 = 0.f, a1 = 0.f, a2 = 0.f, a3 = 0.f;
#pragma unroll 4
    for (int k = 0; k < 64; ++k) {
        float xv = Xs[k * 33 + tr];
        int wb = k * 32 + tc * 4;
        a0 = fmaf(xv, Ws[wb + 0], a0);
        a1 = fmaf(xv, Ws[wb + 1], a1);
        a2 = fmaf(xv, Ws[wb + 2], a2);
        a3 = fmaf(xv, Ws[wb + 3], a3);
    }
    int n = n0 + tr;
    if (n < NN) {
        float s = g_dinv[n];
        size_t o = (size_t)n * 32 + tc * 4;
        g_hs2[o + 0] = a0 * s;  g_acc2[o + 0] = a0 * s;
        g_hs2[o + 1] = a1 * s;  g_acc2[o + 1] = a1 * s;
        g_hs2[o + 2] = a2 * s;  g_acc2[o + 2] = a2 * s;
        g_hs2[o + 3] = a3 * s;  g_acc2[o + 3] = a3 * s;
    }
}

// ---------------- edge scatter: acc[dst*C+c] += hs[src*C+c] ----------------
__global__ void scatter1_kernel(const void* ei, int E) {
    int is64 = (g_oddor == 0u);
    long long t = (long long)blockIdx.x * blockDim.x + threadIdx.x;
    int e = (int)(t >> 6), c = (int)(t & 63);
    if (e >= E) return;
    int s = edge_at(ei, is64, e);
    int d = edge_at(ei, is64, (long long)E + e);
    if ((unsigned)s >= NN || (unsigned)d >= NN) return;
    atomicAdd(&g_acc1[(size_t)d * 64 + c], g_hs1[(size_t)s * 64 + c]);
}

__global__ void scatter2_kernel(const void* ei, int E) {
    int is64 = (g_oddor == 0u);
    long long t = (long long)blockIdx.x * blockDim.x + threadIdx.x;
    int e = (int)(t >> 5), c = (int)(t & 31);
    if (e >= E) return;
    int s = edge_at(ei, is64, e);
    int d = edge_at(ei, is64, (long long)E + e);
    if ((unsigned)s >= NN || (unsigned)d >= NN) return;
    atomicAdd(&g_acc2[(size_t)d * 32 + c], g_hs2[(size_t)s * 32 + c]);
}

// ---------------- finalize layer 1: bias + relu + PARTITIONABLE-threefry dropout ----------------
// JAX >= 0.4.36 default: bits[i] = x0 ^ x1 of threefry2x32(key, (i >> 32, i & 0xffffffff)).
// Here size < 2^32 so counts = (0, i).
__global__ void finalize1_kernel(const float* b1) {
    int j = blockIdx.x * blockDim.x + threadIdx.x;
    if (j >= NN * 64) return;
    uint32_t o0, o1;
    threefry_0_42(0u, (uint32_t)j, o0, o1);
    uint32_t bits = o0 ^ o1;
    int n = j >> 6, c = j & 63;
    float v = g_dinv[n] * g_acc1[j] + b1[c];
    v = fmaxf(v, 0.0f);
    g_h1d[j] = jax_keep(bits) ? v * 1.25f : 0.0f;
}

// ---------------- finalize layer 2: bias only ----------------
__global__ void finalize2_kernel(const float* b2, float* out) {
    int j = blockIdx.x * blockDim.x + threadIdx.x;
    if (j >= NN * 32) return;
    int n = j >> 5, c = j & 31;
    out[j] = g_dinv[n] * g_acc2[j] + b2[c];
}

// ---------------- launch: kernel launches ONLY ----------------
extern "C" void kernel_launch(void* const* d_in, const int* in_sizes, int n_in,
                              void* d_out, int out_size) {
    const float* x  = (const float*)d_in[0];
    const void*  ei = d_in[1];
    const float* W1 = (const float*)d_in[2];
    const float* b1 = (const float*)d_in[3];
    const float* W2 = (const float*)d_in[4];
    const float* b2 = (const float*)d_in[5];
    float*       out = (float*)d_out;

    const int N = NN;
    const int E = in_sizes[1] / 2;
    const long long safe_words = (long long)in_sizes[1];

    // 0) edge_index dtype detection (int32 vs int64)
    reset_flag_kernel<<<1, 1>>>();
    detect_kernel<<<512, 256>>>((const unsigned*)ei, safe_words);

    // 1) degree (self-loop folded via init=1.0), then dinv = rsqrt(deg)
    fill_one_kernel<<<(N + 255) / 256, 256>>>(N);
    deg_kernel<<<(E + 255) / 256, 256>>>(ei, E);
    rsqrt_kernel<<<(N + 255) / 256, 256>>>(N);

    // 2) layer 1 GEMM (+dinv pre-scale)
    gemm1_kernel<<<(N + 15) / 16, 256>>>(x, W1);

    // 3) scatter layer 1
    {
        long long th = (long long)E * 64;
        scatter1_kernel<<<(unsigned)((th + 255) / 256), 256>>>(ei, E);
    }

    // 4) bias + relu + dropout (partitionable threefry stream)
    finalize1_kernel<<<(N * 64 + 255) / 256, 256>>>(b1);

    // 5) layer 2 GEMM
    gemm2_kernel<<<(N + 31) / 32, 256>>>(W2);

    // 6) scatter layer 2
    {
        long long th = (long long)E * 32;
        scatter2_kernel<<<(unsigned)((th + 255) / 256), 256>>>(ei, E);
    }

    // 7) out = dinv*acc2 + b2
    finalize2_kernel<<<(N * 32 + 255) / 256, 256>>>(b2, out);
}

// round 7
// speedup vs baseline: 2.3908x; 2.3908x over previous
#include <cuda_runtime.h>
#include <cstdint>

#define NN 100000
#define EMAX 1700000
#define NB 391            // ceil(NN/256)

// ---------------- scratch: static __device__ globals ----------------
__device__ float  g_dinv[NN];
__device__ int    g_cnt [NN];         // in-degree (no self-loop)
__device__ int    g_rowptr[NN];       // CSR row start
__device__ int    g_fill[NN];         // fill cursor for CSR build
__device__ int    g_bsum[NB];         // block sums for scan
__device__ int    g_csr [EMAX];       // src indices sorted by dst
__device__ float4 g_hs1 [NN * 16];    // (x@W1)*dinv   [N,64]
__device__ float4 g_h1d [NN * 16];    // relu+dropout  [N,64]
__device__ float4 g_hs2 [NN * 8];     // (h1d@W2)*dinv [N,32]
__device__ unsigned g_oddor;          // ==0 -> edge_index int64, !=0 -> int32

// ---------------- edge index accessor (dtype decided at runtime) ----------------
__device__ __forceinline__ int edge_at(const void* ei, int is64, long long idx) {
    if (is64) return (int)((const long long*)ei)[idx];
    return ((const int*)ei)[idx];
}

// ---------------- dtype detection ----------------
__global__ void reset_kernel() {
    int i = blockIdx.x * blockDim.x + threadIdx.x;
    if (i == 0) g_oddor = 0u;
    if (i < NN) g_cnt[i] = 0;
}

__global__ void detect_kernel(const unsigned* w, long long nwords) {
    long long stride = (long long)gridDim.x * blockDim.x;
    unsigned acc = 0;
    for (long long i = (long long)blockIdx.x * blockDim.x + threadIdx.x;
         2 * i + 1 < nwords; i += stride)
        acc |= w[2 * i + 1];
    for (int o = 16; o > 0; o >>= 1) acc |= __shfl_down_sync(0xffffffffu, acc, o);
    if ((threadIdx.x & 31) == 0 && acc) atomicOr(&g_oddor, acc);
}

// ---------------- JAX Threefry-2x32, key = (0, 42) ----------------
__device__ __forceinline__ void threefry_0_42(uint32_t c0, uint32_t c1,
                                              uint32_t& o0, uint32_t& o1) {
    const uint32_t ks0 = 0u;
    const uint32_t ks1 = 42u;
    const uint32_t ks2 = 0x1BD11BDAu ^ 0u ^ 42u;
    uint32_t x0 = c0 + ks0;
    uint32_t x1 = c1 + ks1;
#define TF_RND(r) { x0 += x1; x1 = (x1 << (r)) | (x1 >> (32 - (r))); x1 ^= x0; }
    TF_RND(13) TF_RND(15) TF_RND(26) TF_RND(6)
    x0 += ks1; x1 += ks2 + 1u;
    TF_RND(17) TF_RND(29) TF_RND(16) TF_RND(24)
    x0 += ks2; x1 += ks0 + 2u;
    TF_RND(13) TF_RND(15) TF_RND(26) TF_RND(6)
    x0 += ks0; x1 += ks1 + 3u;
    TF_RND(17) TF_RND(29) TF_RND(16) TF_RND(24)
    x0 += ks1; x1 += ks2 + 4u;
    TF_RND(13) TF_RND(15) TF_RND(26) TF_RND(6)
    x0 += ks2; x1 += ks0 + 5u;
#undef TF_RND
    o0 = x0; o1 = x1;
}

__device__ __forceinline__ bool jax_keep(uint32_t bits) {
    float f = __uint_as_float((bits >> 9) | 0x3f800000u) - 1.0f;
    return f < 0.8f;
}

// ---------------- degree / dinv ----------------
__global__ void deg_cnt_kernel(const void* ei, int E) {
    int is64 = (g_oddor == 0u);
    int e = blockIdx.x * blockDim.x + threadIdx.x;
    if (e < E) {
        int d = edge_at(ei, is64, (long long)E + e);
        if ((unsigned)d < NN) atomicAdd(&g_cnt[d], 1);
    }
}

__global__ void dinv_kernel() {
    int i = blockIdx.x * blockDim.x + threadIdx.x;
    if (i < NN) g_dinv[i] = rsqrtf(1.0f + (float)g_cnt[i]);   // +1 = self-loop
}

// ---------------- exclusive scan of g_cnt -> g_rowptr (two-level) ----------------
__global__ void scan1_kernel() {
    __shared__ int s[256];
    int i = blockIdx.x * 256 + threadIdx.x;
    int v = (i < NN) ? g_cnt[i] : 0;
    s[threadIdx.x] = v;
    __syncthreads();
    for (int o = 1; o < 256; o <<= 1) {
        int t = (threadIdx.x >= o) ? s[threadIdx.x - o] : 0;
        __syncthreads();
        s[threadIdx.x] += t;
        __syncthreads();
    }
    if (i < NN) g_rowptr[i] = s[threadIdx.x] - v;   // exclusive
    if (threadIdx.x == 255) g_bsum[blockIdx.x] = s[255];
}

__global__ void scan2_kernel() {
    __shared__ int s[512];
    int tid = threadIdx.x;
    int v = (tid < NB) ? g_bsum[tid] : 0;
    s[tid] = v;
    __syncthreads();
    for (int o = 1; o < 512; o <<= 1) {
        int t = (tid >= o) ? s[tid - o] : 0;
        __syncthreads();
        s[tid] += t;
        __syncthreads();
    }
    if (tid < NB) g_bsum[tid] = s[tid] - v;         // exclusive block offsets
}

__global__ void scan3_kernel() {
    int i = blockIdx.x * 256 + threadIdx.x;
    if (i < NN) {
        int r = g_rowptr[i] + g_bsum[blockIdx.x];
        g_rowptr[i] = r;
        g_fill[i]   = r;
    }
}

// ---------------- CSR build: csr[pos] = src, grouped by dst ----------------
__global__ void build_kernel(const void* ei, int E) {
    int is64 = (g_oddor == 0u);
    int e = blockIdx.x * blockDim.x + threadIdx.x;
    if (e >= E) return;
    int s = edge_at(ei, is64, e);
    int d = edge_at(ei, is64, (long long)E + e);
    if ((unsigned)s >= NN || (unsigned)d >= NN) return;
    int pos = atomicAdd(&g_fill[d], 1);
    if (pos < EMAX) g_csr[pos] = s;
}

// ---------------- GEMM layer 1: hs1 = (X @ W1) * dinv  (K=128, C=64) ----------------
__global__ void gemm1_kernel(const float* X, const float* W) {
    __shared__ float Ws[128 * 64];
    __shared__ float Xs[128 * 17];
    const int tid = threadIdx.x;
    const int n0  = blockIdx.x * 16;
    float* hs = (float*)g_hs1;

    for (int i = tid; i < 128 * 64; i += 256) Ws[i] = W[i];
    for (int i = tid; i < 16 * 128; i += 256) {
        int r = i >> 7, k = i & 127;
        Xs[k * 17 + r] = X[(size_t)(n0 + r) * 128 + k];
    }
    __syncthreads();

    const int tc = tid & 15;
    const int tr = tid >> 4;
    float a0 = 0.f, a1 = 0.f, a2 = 0.f, a3 = 0.f;
#pragma unroll 4
    for (int k = 0; k < 128; ++k) {
        float xv = Xs[k * 17 + tr];
        int wb = k * 64 + tc * 4;
        a0 = fmaf(xv, Ws[wb + 0], a0);
        a1 = fmaf(xv, Ws[wb + 1], a1);
        a2 = fmaf(xv, Ws[wb + 2], a2);
        a3 = fmaf(xv, Ws[wb + 3], a3);
    }
    int n = n0 + tr;
    if (n < NN) {
        float s = g_dinv[n];
        size_t o = (size_t)n * 64 + tc * 4;
        hs[o + 0] = a0 * s;
        hs[o + 1] = a1 * s;
        hs[o + 2] = a2 * s;
        hs[o + 3] = a3 * s;
    }
}

// ---------------- aggregate layer 1 + bias + relu + dropout (warp per node) ----------------
__global__ void agg1_kernel(const float* b1) {
    int gw = (blockIdx.x * blockDim.x + threadIdx.x) >> 5;
    if (gw >= NN) return;
    const int lane = threadIdx.x & 31;
    const int n = gw;
    const float2* hs = (const float2*)g_hs1;

    float2 acc = hs[(size_t)n * 32 + lane];          // self-loop term
    const int start = g_rowptr[n];
    const int cnt   = g_cnt[n];

    int i = 0;
    for (; i + 4 <= cnt; i += 4) {
        int s0 = g_csr[start + i + 0];
        int s1 = g_csr[start + i + 1];
        int s2 = g_csr[start + i + 2];
        int s3 = g_csr[start + i + 3];
        float2 v0 = hs[(size_t)s0 * 32 + lane];
        float2 v1 = hs[(size_t)s1 * 32 + lane];
        float2 v2 = hs[(size_t)s2 * 32 + lane];
        float2 v3 = hs[(size_t)s3 * 32 + lane];
        acc.x += (v0.x + v1.x) + (v2.x + v3.x);
        acc.y += (v0.y + v1.y) + (v2.y + v3.y);
    }
    for (; i < cnt; ++i) {
        int s = g_csr[start + i];
        float2 v = hs[(size_t)s * 32 + lane];
        acc.x += v.x; acc.y += v.y;
    }

    const float di = g_dinv[n];
    const int c0 = lane * 2;
    float vx = fmaxf(di * acc.x + b1[c0 + 0], 0.0f);
    float vy = fmaxf(di * acc.y + b1[c0 + 1], 0.0f);

    int j = n * 64 + c0;
    uint32_t a0, a1, b0, b1w;
    threefry_0_42(0u, (uint32_t)j,     a0, a1);
    threefry_0_42(0u, (uint32_t)(j+1), b0, b1w);
    float2 o;
    o.x = jax_keep(a0 ^ a1)  ? vx * 1.25f : 0.0f;
    o.y = jax_keep(b0 ^ b1w) ? vy * 1.25f : 0.0f;
    ((float2*)g_h1d)[(size_t)n * 32 + lane] = o;
}

// ---------------- GEMM layer 2: hs2 = (h1d @ W2) * dinv  (K=64, C=32) ----------------
__global__ void gemm2_kernel(const float* W) {
    __shared__ float Ws[64 * 32];
    __shared__ float Xs[64 * 33];
    const int tid = threadIdx.x;
    const int n0  = blockIdx.x * 32;
    const float* h1d = (const float*)g_h1d;
    float* hs = (float*)g_hs2;

    for (int i = tid; i < 64 * 32; i += 256) Ws[i] = W[i];
    for (int i = tid; i < 32 * 64; i += 256) {
        int r = i >> 6, k = i & 63;
        Xs[k * 33 + r] = h1d[(size_t)(n0 + r) * 64 + k];
    }
    __syncthreads();

    const int tc = tid & 7;
    const int tr = tid >> 3;
    float a0 = 0.f, a1 = 0.f, a2 = 0.f, a3 = 0.f;
#pragma unroll 4
    for (int k = 0; k < 64; ++k) {
        float xv = Xs[k * 33 + tr];
        int wb = k * 32 + tc * 4;
        a0 = fmaf(xv, Ws[wb + 0], a0);
        a1 = fmaf(xv, Ws[wb + 1], a1);
        a2 = fmaf(xv, Ws[wb + 2], a2);
        a3 = fmaf(xv, Ws[wb + 3], a3);
    }
    int n = n0 + tr;
    if (n < NN) {
        float s = g_dinv[n];
        size_t o = (size_t)n * 32 + tc * 4;
        hs[o + 0] = a0 * s;
        hs[o + 1] = a1 * s;
        hs[o + 2] = a2 * s;
        hs[o + 3] = a3 * s;
    }
}

// ---------------- aggregate layer 2 + bias (warp per node) ----------------
__global__ void agg2_kernel(const float* b2, float* out) {
    int gw = (blockIdx.x * blockDim.x + threadIdx.x) >> 5;
    if (gw >= NN) return;
    const int lane = threadIdx.x & 31;
    const int n = gw;
    const float* hs = (const float*)g_hs2;

    float acc = hs[(size_t)n * 32 + lane];           // self-loop term
    const int start = g_rowptr[n];
    const int cnt   = g_cnt[n];

    int i = 0;
    for (; i + 4 <= cnt; i += 4) {
        int s0 = g_csr[start + i + 0];
        int s1 = g_csr[start + i + 1];
        int s2 = g_csr[start + i + 2];
        int s3 = g_csr[start + i + 3];
        float v0 = hs[(size_t)s0 * 32 + lane];
        float v1 = hs[(size_t)s1 * 32 + lane];
        float v2 = hs[(size_t)s2 * 32 + lane];
        float v3 = hs[(size_t)s3 * 32 + lane];
        acc += (v0 + v1) + (v2 + v3);
    }
    for (; i < cnt; ++i) {
        int s = g_csr[start + i];
        acc += hs[(size_t)s * 32 + lane];
    }

    out[(size_t)n * 32 + lane] = g_dinv[n] * acc + b2[lane];
}

// ---------------- launch: kernel launches ONLY ----------------
extern "C" void kernel_launch(void* const* d_in, const int* in_sizes, int n_in,
                              void* d_out, int out_size) {
    const float* x  = (const float*)d_in[0];
    const void*  ei = d_in[1];
    const float* W1 = (const float*)d_in[2];
    const float* b1 = (const float*)d_in[3];
    const float* W2 = (const float*)d_in[4];
    const float* b2 = (const float*)d_in[5];
    float*       out = (float*)d_out;

    const int N = NN;
    const int E = in_sizes[1] / 2;
    const long long safe_words = (long long)in_sizes[1];

    // 0) reset + dtype detection
    reset_kernel<<<NB, 256>>>();
    detect_kernel<<<512, 256>>>((const unsigned*)ei, safe_words);

    // 1) degree counts, dinv
    deg_cnt_kernel<<<(E + 255) / 256, 256>>>(ei, E);
    dinv_kernel<<<NB, 256>>>();

    // 2) CSR build: exclusive scan + fill
    scan1_kernel<<<NB, 256>>>();
    scan2_kernel<<<1, 512>>>();
    scan3_kernel<<<NB, 256>>>();
    build_kernel<<<(E + 255) / 256, 256>>>(ei, E);

    // 3) layer 1: GEMM -> gather-aggregate (+bias/relu/dropout fused)
    gemm1_kernel<<<(N + 15) / 16, 256>>>(x, W1);
    agg1_kernel<<<(N * 32 + 255) / 256, 256>>>(b1);

    // 4) layer 2: GEMM -> gather-aggregate (+bias fused)
    gemm2_kernel<<<(N + 31) / 32, 256>>>(W2);
    agg2_kernel<<<(N * 32 + 255) / 256, 256>>>(b2, out);
}

// round 8
// speedup vs baseline: 3.6813x; 1.5398x over previous
#include <cuda_runtime.h>
#include <cstdint>

#define NN 100000
#define EMAX 1700000
#define NB 391            // ceil(NN/256)

// ---------------- scratch: static __device__ globals ----------------
__device__ float  g_dinv[NN];
__device__ int    g_cnt [NN];         // in-degree (no self-loop)
__device__ int    g_rowptr[NN];       // CSR row start
__device__ int    g_fill[NN];         // fill cursor for CSR build
__device__ int    g_bsum[NB];         // block sums for scan
__device__ int    g_csr [EMAX];       // src indices sorted by dst
__device__ float4 g_hs1 [NN * 16];    // (x@W1)*dinv   [N,64]
__device__ float4 g_h1d [NN * 16];    // relu+dropout  [N,64]
__device__ float4 g_hs2 [NN * 8];     // (h1d@W2)*dinv [N,32]
__device__ unsigned g_oddor;          // ==0 -> edge_index int64, !=0 -> int32

// ---------------- edge index accessor ----------------
__device__ __forceinline__ int edge_at(const void* ei, int is64, long long idx) {
    if (is64) return (int)((const long long*)ei)[idx];
    return ((const int*)ei)[idx];
}

// ---------------- reset + dtype detection ----------------
__global__ void reset_kernel() {
    int i = blockIdx.x * blockDim.x + threadIdx.x;
    if (i == 0) g_oddor = 0u;
    if (i < NN) g_cnt[i] = 0;
}

__global__ void detect_kernel(const unsigned* w, long long nwords) {
    long long stride = (long long)gridDim.x * blockDim.x;
    unsigned acc = 0;
    for (long long i = (long long)blockIdx.x * blockDim.x + threadIdx.x;
         2 * i + 1 < nwords; i += stride)
        acc |= w[2 * i + 1];
    for (int o = 16; o > 0; o >>= 1) acc |= __shfl_down_sync(0xffffffffu, acc, o);
    if ((threadIdx.x & 31) == 0 && acc) atomicOr(&g_oddor, acc);
}

// ---------------- JAX Threefry-2x32, key = (0, 42) ----------------
__device__ __forceinline__ void threefry_0_42(uint32_t c0, uint32_t c1,
                                              uint32_t& o0, uint32_t& o1) {
    const uint32_t ks0 = 0u;
    const uint32_t ks1 = 42u;
    const uint32_t ks2 = 0x1BD11BDAu ^ 0u ^ 42u;
    uint32_t x0 = c0 + ks0;
    uint32_t x1 = c1 + ks1;
#define TF_RND(r) { x0 += x1; x1 = (x1 << (r)) | (x1 >> (32 - (r))); x1 ^= x0; }
    TF_RND(13) TF_RND(15) TF_RND(26) TF_RND(6)
    x0 += ks1; x1 += ks2 + 1u;
    TF_RND(17) TF_RND(29) TF_RND(16) TF_RND(24)
    x0 += ks2; x1 += ks0 + 2u;
    TF_RND(13) TF_RND(15) TF_RND(26) TF_RND(6)
    x0 += ks0; x1 += ks1 + 3u;
    TF_RND(17) TF_RND(29) TF_RND(16) TF_RND(24)
    x0 += ks1; x1 += ks2 + 4u;
    TF_RND(13) TF_RND(15) TF_RND(26) TF_RND(6)
    x0 += ks2; x1 += ks0 + 5u;
#undef TF_RND
    o0 = x0; o1 = x1;
}

__device__ __forceinline__ bool jax_keep(uint32_t bits) {
    float f = __uint_as_float((bits >> 9) | 0x3f800000u) - 1.0f;
    return f < 0.8f;
}

// ---------------- degree counts ----------------
__global__ void deg_cnt_kernel(const void* ei, int E) {
    int is64 = (g_oddor == 0u);
    int e = blockIdx.x * blockDim.x + threadIdx.x;
    if (e < E) {
        int d = edge_at(ei, is64, (long long)E + e);
        if ((unsigned)d < NN) atomicAdd(&g_cnt[d], 1);
    }
}

// ---------------- scan level 1 (also computes dinv) ----------------
__global__ void scan1_kernel() {
    __shared__ int s[256];
    int i = blockIdx.x * 256 + threadIdx.x;
    int v = (i < NN) ? g_cnt[i] : 0;
    if (i < NN) g_dinv[i] = rsqrtf(1.0f + (float)v);   // fused: +1 self-loop
    s[threadIdx.x] = v;
    __syncthreads();
    for (int o = 1; o < 256; o <<= 1) {
        int t = (threadIdx.x >= o) ? s[threadIdx.x - o] : 0;
        __syncthreads();
        s[threadIdx.x] += t;
        __syncthreads();
    }
    if (i < NN) g_rowptr[i] = s[threadIdx.x] - v;   // exclusive
    if (threadIdx.x == 255) g_bsum[blockIdx.x] = s[255];
}

__global__ void scan2_kernel() {
    __shared__ int s[512];
    int tid = threadIdx.x;
    int v = (tid < NB) ? g_bsum[tid] : 0;
    s[tid] = v;
    __syncthreads();
    for (int o = 1; o < 512; o <<= 1) {
        int t = (tid >= o) ? s[tid - o] : 0;
        __syncthreads();
        s[tid] += t;
        __syncthreads();
    }
    if (tid < NB) g_bsum[tid] = s[tid] - v;
}

__global__ void scan3_kernel() {
    int i = blockIdx.x * 256 + threadIdx.x;
    if (i < NN) {
        int r = g_rowptr[i] + g_bsum[blockIdx.x];
        g_rowptr[i] = r;
        g_fill[i]   = r;
    }
}

// ---------------- CSR build ----------------
__global__ void build_kernel(const void* ei, int E) {
    int is64 = (g_oddor == 0u);
    int e = blockIdx.x * blockDim.x + threadIdx.x;
    if (e >= E) return;
    int s = edge_at(ei, is64, e);
    int d = edge_at(ei, is64, (long long)E + e);
    if ((unsigned)s >= NN || (unsigned)d >= NN) return;
    int pos = atomicAdd(&g_fill[d], 1);
    if (pos < EMAX) g_csr[pos] = s;
}

// ---------------- GEMM layer 1: hs1 = (X @ W1) * dinv  (K=128, C=64) ----------------
// 256 threads, 64 rows/block, 4x4 thread tile, K-chunks of 16.
__global__ void gemm1_kernel(const float* __restrict__ X, const float* __restrict__ W) {
    __shared__ float Ws[128 * 64];          // 32 KB (full W)
    __shared__ float Xs[16 * 68];           // K-chunk of X, transposed, pad 68
    const int tid = threadIdx.x;
    const int n0  = blockIdx.x * 64;
    float* hs = (float*)g_hs1;

    for (int i = tid; i < 128 * 64 / 4; i += 256)
        ((float4*)Ws)[i] = ((const float4*)W)[i];

    const int tc = tid & 15;                // col group 0..15
    const int tr = tid >> 4;                // row group 0..15
    const int lr = tid >> 2;                // load row 0..63
    const int lq = tid & 3;                 // load quad 0..3

    float a[4][4] = {};

    for (int kc = 0; kc < 128; kc += 16) {
        __syncthreads();
        // load X[n0+lr][kc+lq*4 .. +3], store transposed
        {
            int n = n0 + lr;
            float4 v = make_float4(0.f, 0.f, 0.f, 0.f);
            if (n < NN) v = *(const float4*)(X + (size_t)n * 128 + kc + lq * 4);
            Xs[(lq * 4 + 0) * 68 + lr] = v.x;
            Xs[(lq * 4 + 1) * 68 + lr] = v.y;
            Xs[(lq * 4 + 2) * 68 + lr] = v.z;
            Xs[(lq * 4 + 3) * 68 + lr] = v.w;
        }
        __syncthreads();
#pragma unroll
        for (int k = 0; k < 16; ++k) {
            float4 xv = *(const float4*)(&Xs[k * 68 + tr * 4]);
            float4 wv = *(const float4*)(&Ws[(kc + k) * 64 + tc * 4]);
            float xr[4] = {xv.x, xv.y, xv.z, xv.w};
            float wr[4] = {wv.x, wv.y, wv.z, wv.w};
#pragma unroll
            for (int i = 0; i < 4; ++i)
#pragma unroll
                for (int j = 0; j < 4; ++j)
                    a[i][j] = fmaf(xr[i], wr[j], a[i][j]);
        }
    }

#pragma unroll
    for (int i = 0; i < 4; ++i) {
        int n = n0 + tr * 4 + i;
        if (n < NN) {
            float s = g_dinv[n];
            float4 o = make_float4(a[i][0] * s, a[i][1] * s, a[i][2] * s, a[i][3] * s);
            *(float4*)(hs + (size_t)n * 64 + tc * 4) = o;
        }
    }
}

// ---------------- aggregate layer 1 + bias + relu + dropout (warp/node) ----------------
__global__ void agg1_kernel(const float* __restrict__ b1) {
    int gw = (blockIdx.x * blockDim.x + threadIdx.x) >> 5;
    if (gw >= NN) return;
    const int lane = threadIdx.x & 31;
    const int n = gw;
    const float2* hs = (const float2*)g_hs1;

    float2 acc = __ldg(&hs[(size_t)n * 32 + lane]);   // self-loop term
    const int start = g_rowptr[n];
    const int cnt   = g_cnt[n];

    int i = 0;
    for (; i + 8 <= cnt; i += 8) {
        int s[8];
#pragma unroll
        for (int u = 0; u < 8; ++u) s[u] = __ldg(&g_csr[start + i + u]);
        float2 v[8];
#pragma unroll
        for (int u = 0; u < 8; ++u) v[u] = __ldg(&hs[(size_t)s[u] * 32 + lane]);
        float sx = ((v[0].x + v[1].x) + (v[2].x + v[3].x)) +
                   ((v[4].x + v[5].x) + (v[6].x + v[7].x));
        float sy = ((v[0].y + v[1].y) + (v[2].y + v[3].y)) +
                   ((v[4].y + v[5].y) + (v[6].y + v[7].y));
        acc.x += sx; acc.y += sy;
    }
    for (; i < cnt; ++i) {
        int s = __ldg(&g_csr[start + i]);
        float2 v = __ldg(&hs[(size_t)s * 32 + lane]);
        acc.x += v.x; acc.y += v.y;
    }

    const float di = g_dinv[n];
    const int c0 = lane * 2;
    float vx = fmaxf(di * acc.x + b1[c0 + 0], 0.0f);
    float vy = fmaxf(di * acc.y + b1[c0 + 1], 0.0f);

    int j = n * 64 + c0;
    uint32_t a0, a1, b0, b1w;
    threefry_0_42(0u, (uint32_t)j,     a0, a1);
    threefry_0_42(0u, (uint32_t)(j+1), b0, b1w);
    float2 o;
    o.x = jax_keep(a0 ^ a1)  ? vx * 1.25f : 0.0f;
    o.y = jax_keep(b0 ^ b1w) ? vy * 1.25f : 0.0f;
    ((float2*)g_h1d)[(size_t)n * 32 + lane] = o;
}

// ---------------- GEMM layer 2: hs2 = (h1d @ W2) * dinv  (K=64, C=32) ----------------
// 256 threads, 128 rows/block, 4x4 thread tile, K-chunks of 16.
__global__ void gemm2_kernel(const float* __restrict__ W) {
    __shared__ float Ws[64 * 32];           // 8 KB (full W)
    __shared__ float Xs[16 * 132];          // K-chunk of h1d, transposed, pad 132
    const int tid = threadIdx.x;
    const int n0  = blockIdx.x * 128;
    const float* X = (const float*)g_h1d;
    float* hs = (float*)g_hs2;

    for (int i = tid; i < 64 * 32 / 4; i += 256)
        ((float4*)Ws)[i] = ((const float4*)W)[i];

    const int tc = tid & 7;                 // col group 0..7
    const int tr = tid >> 3;                // row group 0..31
    const int lr2 = tid >> 1;               // load row /2
    const int lq2 = tid & 1;                // which half of 8 k's

    float a[4][4] = {};

    for (int kc = 0; kc < 64; kc += 16) {
        __syncthreads();
        // load rows n0..n0+127, k = kc..kc+15: 128*4 float4; 2 float4/thread
        {
#pragma unroll
            for (int h = 0; h < 2; ++h) {
                int r = lr2;                       // row 0..127
                int q = lq2 * 2 + h;               // quad 0..3
                int n = n0 + r;
                float4 v = make_float4(0.f, 0.f, 0.f, 0.f);
                if (n < NN) v = *(const float4*)(X + (size_t)n * 64 + kc + q * 4);
                Xs[(q * 4 + 0) * 132 + r] = v.x;
                Xs[(q * 4 + 1) * 132 + r] = v.y;
                Xs[(q * 4 + 2) * 132 + r] = v.z;
                Xs[(q * 4 + 3) * 132 + r] = v.w;
            }
        }
        __syncthreads();
#pragma unroll
        for (int k = 0; k < 16; ++k) {
            float4 xv = *(const float4*)(&Xs[k * 132 + tr * 4]);
            float4 wv = *(const float4*)(&Ws[(kc + k) * 32 + tc * 4]);
            float xr[4] = {xv.x, xv.y, xv.z, xv.w};
            float wr[4] = {wv.x, wv.y, wv.z, wv.w};
#pragma unroll
            for (int i = 0; i < 4; ++i)
#pragma unroll
                for (int j = 0; j < 4; ++j)
                    a[i][j] = fmaf(xr[i], wr[j], a[i][j]);
        }
    }

#pragma unroll
    for (int i = 0; i < 4; ++i) {
        int n = n0 + tr * 4 + i;
        if (n < NN) {
            float s = g_dinv[n];
            float4 o = make_float4(a[i][0] * s, a[i][1] * s, a[i][2] * s, a[i][3] * s);
            *(float4*)(hs + (size_t)n * 32 + tc * 4) = o;
        }
    }
}

// ---------------- aggregate layer 2 + bias (warp/node) ----------------
__global__ void agg2_kernel(const float* __restrict__ b2, float* __restrict__ out) {
    int gw = (blockIdx.x * blockDim.x + threadIdx.x) >> 5;
    if (gw >= NN) return;
    const int lane = threadIdx.x & 31;
    const int n = gw;
    const float* hs = (const float*)g_hs2;

    float acc = __ldg(&hs[(size_t)n * 32 + lane]);    // self-loop term
    const int start = g_rowptr[n];
    const int cnt   = g_cnt[n];

    int i = 0;
    for (; i + 8 <= cnt; i += 8) {
        int s[8];
#pragma unroll
        for (int u = 0; u < 8; ++u) s[u] = __ldg(&g_csr[start + i + u]);
        float v[8];
#pragma unroll
        for (int u = 0; u < 8; ++u) v[u] = __ldg(&hs[(size_t)s[u] * 32 + lane]);
        acc += ((v[0] + v[1]) + (v[2] + v[3])) + ((v[4] + v[5]) + (v[6] + v[7]));
    }
    for (; i < cnt; ++i) {
        int s = __ldg(&g_csr[start + i]);
        acc += __ldg(&hs[(size_t)s * 32 + lane]);
    }

    out[(size_t)n * 32 + lane] = g_dinv[n] * acc + b2[lane];
}

// ---------------- launch ----------------
extern "C" void kernel_launch(void* const* d_in, const int* in_sizes, int n_in,
                              void* d_out, int out_size) {
    const float* x  = (const float*)d_in[0];
    const void*  ei = d_in[1];
    const float* W1 = (const float*)d_in[2];
    const float* b1 = (const float*)d_in[3];
    const float* W2 = (const float*)d_in[4];
    const float* b2 = (const float*)d_in[5];
    float*       out = (float*)d_out;

    const int N = NN;
    const int E = in_sizes[1] / 2;
    const long long safe_words = (long long)in_sizes[1];

    reset_kernel<<<NB, 256>>>();
    detect_kernel<<<512, 256>>>((const unsigned*)ei, safe_words);

    deg_cnt_kernel<<<(E + 255) / 256, 256>>>(ei, E);

    scan1_kernel<<<NB, 256>>>();       // also computes dinv
    scan2_kernel<<<1, 512>>>();
    scan3_kernel<<<NB, 256>>>();
    build_kernel<<<(E + 255) / 256, 256>>>(ei, E);

    gemm1_kernel<<<(N + 63) / 64, 256>>>(x, W1);
    agg1_kernel<<<(N * 32 + 255) / 256, 256>>>(b1);

    gemm2_kernel<<<(N + 127) / 128, 256>>>(W2);
    agg2_kernel<<<(N * 32 + 255) / 256, 256>>>(b2, out);
}